// round 7
// baseline (speedup 1.0000x reference)
#include <cuda_runtime.h>
#include <cstdint>
#include <math.h>

#define D_MODEL     2048
#define NUM_EXPERTS 64
#define N_TOKENS    16384
#define BM          128                 // tokens per CTA
#define BK          32                  // K per chunk
#define NCHUNK      (D_MODEL / BK)      // 64
#define THREADS     128                 // 4 warps x 32 tokens
#define ROWU        20                  // 16B units per row (16 data + 4 pad) -> 320B
#define GAP_THRESH  1e-3f               // refine if top-gap below this (500x GEMM err)

// smem: bias 256B | As 128x320 | Bs 64x320 ; epilogue reuses As as L[128][67]
#define SM_BIAS   0
#define SM_AS     256
#define SM_BS     (256 + BM * ROWU * 16)                    // 41216
#define SMEM_TOTAL (SM_BS + NUM_EXPERTS * ROWU * 16)        // 61696
#define LSTRIDE   67                    // odd stride: conflict-free row scan

// refinement records: [token, e0, e1, e2, e3]
__device__ unsigned int g_refine_ctr;
__device__ int g_refine_rec[N_TOKENS * 5];

// ---------------------------------------------------------------------------
static __device__ __forceinline__ uint32_t bf16x2_rn(float lo, float hi) {
    uint32_t r;
    asm("cvt.rn.bf16x2.f32 %0, %1, %2;" : "=r"(r) : "f"(hi), "f"(lo));
    return r;
}
static __device__ __forceinline__ float bf16_lo_f(uint32_t u) {
    return __uint_as_float(u << 16);
}
static __device__ __forceinline__ float bf16_hi_f(uint32_t u) {
    return __uint_as_float(u & 0xffff0000u);
}

// fp32 pair -> 3 bf16 planes (b1+b2+b3 == x exactly), packed {b1, b2, b3, 0}
static __device__ __forceinline__ uint4 split_pair(float x, float y) {
    uint32_t b1 = bf16x2_rn(x, y);
    float r1x = x - bf16_lo_f(b1);
    float r1y = y - bf16_hi_f(b1);
    uint32_t b2 = bf16x2_rn(r1x, r1y);
    float r2x = r1x - bf16_lo_f(b2);
    float r2y = r1y - bf16_hi_f(b2);
    uint32_t b3 = bf16x2_rn(r2x, r2y);
    return make_uint4(b1, b2, b3, 0u);
}

// byte offset of 16B unit for (row, k-pair p); swizzle keeps STS & LDS conflict-free
static __device__ __forceinline__ uint32_t unit_off(int row, int p) {
    return (uint32_t)(row * ROWU + (p ^ (p >> 3))) * 16u;
}

static __device__ __forceinline__ void mma_bf16(float* d,
                                                uint32_t a0, uint32_t a1,
                                                uint32_t a2, uint32_t a3,
                                                uint32_t b0, uint32_t b1) {
    asm volatile(
        "mma.sync.aligned.m16n8k16.row.col.f32.bf16.bf16.f32 "
        "{%0,%1,%2,%3}, {%4,%5,%6,%7}, {%8,%9}, {%0,%1,%2,%3};"
        : "+f"(d[0]), "+f"(d[1]), "+f"(d[2]), "+f"(d[3])
        : "r"(a0), "r"(a1), "r"(a2), "r"(a3), "r"(b0), "r"(b1));
}

// ---------------------------------------------------------------------------
// Kernel 0: reset refinement counter
// ---------------------------------------------------------------------------
__global__ void reset_ctr() { g_refine_ctr = 0u; }

// ---------------------------------------------------------------------------
// Kernel 1: bf16x6 split GEMM (mma.sync m16n8k16) + top-4 epilogue.
// Safe tokens written directly; near-tie tokens flagged for fp64 refinement.
// ---------------------------------------------------------------------------
__global__ __launch_bounds__(THREADS)
void router_gemm(const float* __restrict__ X, const float* __restrict__ W,
                 const float* __restrict__ bias, float* __restrict__ out) {
    extern __shared__ __align__(16) char smem[];
    float* bias_s = (float*)(smem + SM_BIAS);
    char*  As     = smem + SM_AS;
    char*  Bs     = smem + SM_BS;

    const int tid  = threadIdx.x;
    const int wid  = tid >> 5;
    const int lane = tid & 31;
    const int grp  = lane >> 2;     // 0..7
    const int qid  = lane & 3;      // 0..3
    const int token0 = blockIdx.x * BM;

    if (tid < NUM_EXPERTS) bias_s[tid] = bias[tid];

    float acc[2][8][4];
    #pragma unroll
    for (int m = 0; m < 2; m++)
        #pragma unroll
        for (int n = 0; n < 8; n++)
            #pragma unroll
            for (int r = 0; r < 4; r++) acc[m][n][r] = 0.0f;

    float4 xa[8], xb[4];
    #pragma unroll
    for (int r = 0; r < 8; r++) {
        int slot = r * THREADS + tid;
        int t = slot >> 3, kq = slot & 7;
        xa[r] = *(const float4*)(X + (size_t)(token0 + t) * D_MODEL + kq * 4);
    }
    #pragma unroll
    for (int r = 0; r < 4; r++) {
        int slot = r * THREADS + tid;
        int e = slot >> 3, kq = slot & 7;
        xb[r] = *(const float4*)(W + (size_t)e * D_MODEL + kq * 4);
    }

    #pragma unroll 1
    for (int c = 0; c < NCHUNK; c++) {
        __syncthreads();

        #pragma unroll
        for (int r = 0; r < 8; r++) {
            int slot = r * THREADS + tid;
            int t = slot >> 3, kq = slot & 7;
            *(uint4*)(As + unit_off(t, 2 * kq))     = split_pair(xa[r].x, xa[r].y);
            *(uint4*)(As + unit_off(t, 2 * kq + 1)) = split_pair(xa[r].z, xa[r].w);
        }
        #pragma unroll
        for (int r = 0; r < 4; r++) {
            int slot = r * THREADS + tid;
            int e = slot >> 3, kq = slot & 7;
            *(uint4*)(Bs + unit_off(e, 2 * kq))     = split_pair(xb[r].x, xb[r].y);
            *(uint4*)(Bs + unit_off(e, 2 * kq + 1)) = split_pair(xb[r].z, xb[r].w);
        }
        __syncthreads();

        if (c + 1 < NCHUNK) {
            const int k0 = (c + 1) * BK;
            #pragma unroll
            for (int r = 0; r < 8; r++) {
                int slot = r * THREADS + tid;
                int t = slot >> 3, kq = slot & 7;
                xa[r] = *(const float4*)(X + (size_t)(token0 + t) * D_MODEL + k0 + kq * 4);
            }
            #pragma unroll
            for (int r = 0; r < 4; r++) {
                int slot = r * THREADS + tid;
                int e = slot >> 3, kq = slot & 7;
                xb[r] = *(const float4*)(W + (size_t)e * D_MODEL + k0 + kq * 4);
            }
        }

        #pragma unroll
        for (int s = 0; s < 2; s++) {
            const int p0 = s * 8 + qid;
            uint4 ua[2][4];
            #pragma unroll
            for (int m = 0; m < 2; m++) {
                const int r0 = wid * 32 + m * 16 + grp;
                ua[m][0] = *(const uint4*)(As + unit_off(r0,     p0));
                ua[m][1] = *(const uint4*)(As + unit_off(r0 + 8, p0));
                ua[m][2] = *(const uint4*)(As + unit_off(r0,     p0 + 4));
                ua[m][3] = *(const uint4*)(As + unit_off(r0 + 8, p0 + 4));
            }
            #pragma unroll
            for (int n = 0; n < 8; n++) {
                const int e = n * 8 + grp;
                uint4 v0 = *(const uint4*)(Bs + unit_off(e, p0));
                uint4 v1 = *(const uint4*)(Bs + unit_off(e, p0 + 4));
                #pragma unroll
                for (int m = 0; m < 2; m++) {
                    float* d = acc[m][n];
                    mma_bf16(d, ua[m][0].x, ua[m][1].x, ua[m][2].x, ua[m][3].x, v0.x, v1.x); // 1*1
                    mma_bf16(d, ua[m][0].x, ua[m][1].x, ua[m][2].x, ua[m][3].x, v0.y, v1.y); // 1*2
                    mma_bf16(d, ua[m][0].y, ua[m][1].y, ua[m][2].y, ua[m][3].y, v0.x, v1.x); // 2*1
                    mma_bf16(d, ua[m][0].y, ua[m][1].y, ua[m][2].y, ua[m][3].y, v0.y, v1.y); // 2*2
                    mma_bf16(d, ua[m][0].x, ua[m][1].x, ua[m][2].x, ua[m][3].x, v0.z, v1.z); // 1*3
                    mma_bf16(d, ua[m][0].z, ua[m][1].z, ua[m][2].z, ua[m][3].z, v0.x, v1.x); // 3*1
                }
            }
        }
    }

    // ------------------------------------------------------------------
    // epilogue: stage logits in smem, per-token top-4 scan, gap test
    // ------------------------------------------------------------------
    __syncthreads();
    float* L = (float*)(smem + SM_AS);   // L[t][e] at t*LSTRIDE + e
    #pragma unroll
    for (int m = 0; m < 2; m++)
        #pragma unroll
        for (int g = 0; g < 2; g++)
            #pragma unroll
            for (int n = 0; n < 8; n++) {
                int row = wid * 32 + m * 16 + g * 8 + grp;
                int e0  = n * 8 + 2 * qid;
                L[row * LSTRIDE + e0]     = acc[m][n][g * 2 + 0];
                L[row * LSTRIDE + e0 + 1] = acc[m][n][g * 2 + 1];
            }
    __syncthreads();

    {
        const float* Lr = L + tid * LSTRIDE;
        float tv0 = -1e30f, tv1 = -1e30f, tv2 = -1e30f, tv3 = -1e30f;
        int   ti0 = 0, ti1 = 0, ti2 = 0, ti3 = 0;
        #pragma unroll
        for (int e = 0; e < NUM_EXPERTS; e++) {
            float v = Lr[e] + bias_s[e];
            if (v > tv0) {
                tv3 = tv2; ti3 = ti2; tv2 = tv1; ti2 = ti1;
                tv1 = tv0; ti1 = ti0; tv0 = v;  ti0 = e;
            } else if (v > tv1) {
                tv3 = tv2; ti3 = ti2; tv2 = tv1; ti2 = ti1; tv1 = v; ti1 = e;
            } else if (v > tv2) {
                tv3 = tv2; ti3 = ti2; tv2 = v;  ti2 = e;
            } else if (v > tv3) {
                tv3 = v; ti3 = e;
            }
        }

        const int token = token0 + tid;
        if ((tv0 - tv1) < GAP_THRESH || (tv1 - tv2) < GAP_THRESH) {
            unsigned int idx = atomicAdd(&g_refine_ctr, 1u);
            int* rec = &g_refine_rec[idx * 5];
            rec[0] = token; rec[1] = ti0; rec[2] = ti1; rec[3] = ti2; rec[4] = ti3;
        } else {
            float r  = expf(tv1 - tv0);
            float w1 = 1.0f / (1.0f + r);
            float w2 = r / (1.0f + r);
            out[token * 2 + 0] = w1;
            out[token * 2 + 1] = w2;
            out[N_TOKENS * 2 + token * 2 + 0] = (float)ti0;
            out[N_TOKENS * 2 + token * 2 + 1] = (float)ti1;
        }
        // near-tie tokens get placeholder writes from the refine kernel only
        if ((tv0 - tv1) < GAP_THRESH || (tv1 - tv2) < GAP_THRESH) {
            out[token * 2 + 0] = 0.5f;      // overwritten by refine
            out[token * 2 + 1] = 0.5f;
            out[N_TOKENS * 2 + token * 2 + 0] = (float)ti0;
            out[N_TOKENS * 2 + token * 2 + 1] = (float)ti1;
        }
    }
}

// ---------------------------------------------------------------------------
// Kernel 2: fp64 refinement of flagged tokens (one warp per token)
// ---------------------------------------------------------------------------
__global__ __launch_bounds__(256)
void router_refine(const float* __restrict__ X, const float* __restrict__ W,
                   const float* __restrict__ bias, float* __restrict__ out) {
    const unsigned int nrec = g_refine_ctr;
    const int lane  = threadIdx.x & 31;
    const int wgid  = blockIdx.x * (blockDim.x >> 5) + (threadIdx.x >> 5);
    const int wstep = gridDim.x * (blockDim.x >> 5);

    for (unsigned int r = wgid; r < nrec; r += wstep) {
        const int* rec = &g_refine_rec[r * 5];
        const int token = rec[0];
        const float* xr = X + (size_t)token * D_MODEL;

        double lv[4];
        #pragma unroll
        for (int c = 0; c < 4; c++) {
            const int e = rec[1 + c];
            const float* wr = W + (size_t)e * D_MODEL;
            double s = 0.0;
            for (int k = lane; k < D_MODEL; k += 32)
                s += (double)xr[k] * (double)wr[k];
            #pragma unroll
            for (int off = 16; off; off >>= 1)
                s += __shfl_down_sync(0xffffffffu, s, off);
            lv[c] = s + (double)bias[e];     // valid on lane 0
        }

        if (lane == 0) {
            int ei[4] = {rec[1], rec[2], rec[3], rec[4]};
            // insertion sort desc; tie -> lower expert index first
            #pragma unroll
            for (int i = 1; i < 4; i++) {
                double v = lv[i]; int id = ei[i];
                int j = i - 1;
                while (j >= 0 && (lv[j] < v || (lv[j] == v && ei[j] > id))) {
                    lv[j + 1] = lv[j]; ei[j + 1] = ei[j]; j--;
                }
                lv[j + 1] = v; ei[j + 1] = id;
            }
            double rr = exp(lv[1] - lv[0]);
            double w1 = 1.0 / (1.0 + rr);
            double w2 = rr / (1.0 + rr);
            out[token * 2 + 0] = (float)w1;
            out[token * 2 + 1] = (float)w2;
            out[N_TOKENS * 2 + token * 2 + 0] = (float)ei[0];
            out[N_TOKENS * 2 + token * 2 + 1] = (float)ei[1];
        }
    }
}

// ---------------------------------------------------------------------------
extern "C" void kernel_launch(void* const* d_in, const int* in_sizes, int n_in,
                              void* d_out, int out_size) {
    const float* X = (const float*)d_in[0];   // [4, 4096, 2048]
    const float* W = (const float*)d_in[1];   // [64, 2048]
    const float* b = (const float*)d_in[2];   // [64]
    float* out = (float*)d_out;

    cudaFuncSetAttribute(router_gemm,
                         cudaFuncAttributeMaxDynamicSharedMemorySize, SMEM_TOTAL);
    reset_ctr<<<1, 1>>>();
    router_gemm<<<N_TOKENS / BM, THREADS, SMEM_TOTAL>>>(X, W, b, out);
    router_refine<<<128, 256>>>(X, W, b, out);
}

// round 8
// speedup vs baseline: 1.2007x; 1.2007x over previous
#include <cuda_runtime.h>
#include <cstdint>
#include <math.h>

#define D_MODEL     2048
#define NUM_EXPERTS 64
#define N_TOKENS    16384
#define BM          128                 // tokens per CTA
#define BK          32                  // K per chunk
#define NCHUNK      (D_MODEL / BK)      // 64
#define THREADS     256                 // 8 warps x 16 tokens
#define ROWB        160                 // bytes per smem row (128 data + 32 pad)
#define GAP_THRESH  3e-3f               // refine if approx top-gap below this
#define LSTRIDE     65                  // logit staging stride (floats)

// smem: bias 256B | As 128x160 | Bs 64x160 ; epilogue reuses As/Bs as L[128][65]
#define SM_BIAS     0
#define SM_AS       256
#define SM_BS       (256 + BM * ROWB)                 // 20736
#define SMEM_TOTAL  33792                             // >= 256+128*65*4 = 33536

// refinement records: [token, e0, e1, e2, e3]
__device__ unsigned int g_refine_ctr;
__device__ unsigned int g_done_ctr;
__device__ int g_refine_rec[N_TOKENS * 5];

// ---------------------------------------------------------------------------
static __device__ __forceinline__ uint32_t bf16x2_rn(float lo, float hi) {
    uint32_t r;
    asm("cvt.rn.bf16x2.f32 %0, %1, %2;" : "=r"(r) : "f"(hi), "f"(lo));
    return r;
}
static __device__ __forceinline__ float bf16_lo_f(uint32_t u) {
    return __uint_as_float(u << 16);
}
static __device__ __forceinline__ float bf16_hi_f(uint32_t u) {
    return __uint_as_float(u & 0xffff0000u);
}
// fp32 pair -> 2 bf16 planes {b1, b2}
static __device__ __forceinline__ uint2 split_pair(float x, float y) {
    uint32_t b1 = bf16x2_rn(x, y);
    float r1x = x - bf16_lo_f(b1);
    float r1y = y - bf16_hi_f(b1);
    uint32_t b2 = bf16x2_rn(r1x, r1y);
    return make_uint2(b1, b2);
}
static __device__ __forceinline__ uint4 pack4(const float4& v) {
    uint2 p0 = split_pair(v.x, v.y);
    uint2 p1 = split_pair(v.z, v.w);
    return make_uint4(p0.x, p0.y, p1.x, p1.y);
}
// row-major pair fetch: pair p of row at byte row*ROWB + p*8 -> {b1x2, b2x2}
static __device__ __forceinline__ uint2 lds_pair(const char* base, int row, int p) {
    return *(const uint2*)(base + row * ROWB + p * 8);
}

static __device__ __forceinline__ void mma_bf16(float* d,
                                                uint32_t a0, uint32_t a1,
                                                uint32_t a2, uint32_t a3,
                                                uint32_t b0, uint32_t b1) {
    asm volatile(
        "mma.sync.aligned.m16n8k16.row.col.f32.bf16.bf16.f32 "
        "{%0,%1,%2,%3}, {%4,%5,%6,%7}, {%8,%9}, {%0,%1,%2,%3};"
        : "+f"(d[0]), "+f"(d[1]), "+f"(d[2]), "+f"(d[3])
        : "r"(a0), "r"(a1), "r"(a2), "r"(a3), "r"(b0), "r"(b1));
}

// ---------------------------------------------------------------------------
// Kernel 1: bf16x3 split GEMM (mma.sync m16n8k16) + top-4 epilogue.
// Safe tokens written directly; near-tie tokens flagged for fp64 refinement.
// ---------------------------------------------------------------------------
__global__ __launch_bounds__(THREADS)
void router_gemm(const float* __restrict__ X, const float* __restrict__ W,
                 const float* __restrict__ bias, float* __restrict__ out) {
    extern __shared__ __align__(16) char smem[];
    float* bias_s = (float*)(smem + SM_BIAS);
    char*  As     = smem + SM_AS;
    char*  Bs     = smem + SM_BS;

    const int tid  = threadIdx.x;
    const int wid  = tid >> 5;
    const int lane = tid & 31;
    const int grp  = lane >> 2;     // 0..7
    const int qid  = lane & 3;      // 0..3
    const int token0 = blockIdx.x * BM;
    const int r0 = wid * 16 + grp;  // warp tile: 16 tokens x 64 experts

    if (tid < NUM_EXPERTS) bias_s[tid] = bias[tid];

    float acc[8][4];
    #pragma unroll
    for (int n = 0; n < 8; n++)
        #pragma unroll
        for (int r = 0; r < 4; r++) acc[n][r] = 0.0f;

    // register prefetch of chunk 0 (A: 4 float4, B: 2 float4 per thread)
    float4 xa[4], xb[2];
    #pragma unroll
    for (int r = 0; r < 4; r++) {
        int slot = r * THREADS + tid;            // 0..1023
        int t = slot >> 3, kq = slot & 7;
        xa[r] = *(const float4*)(X + (size_t)(token0 + t) * D_MODEL + kq * 4);
    }
    #pragma unroll
    for (int r = 0; r < 2; r++) {
        int slot = r * THREADS + tid;            // 0..511
        int e = slot >> 3, kq = slot & 7;
        xb[r] = *(const float4*)(W + (size_t)e * D_MODEL + kq * 4);
    }

    #pragma unroll 1
    for (int c = 0; c < NCHUNK; c++) {
        __syncthreads();   // previous chunk's smem reads complete

        // ---- split + store chunk c (one STS.128 per float4) ----
        #pragma unroll
        for (int r = 0; r < 4; r++) {
            int slot = r * THREADS + tid;
            int t = slot >> 3, kq = slot & 7;
            *(uint4*)(As + t * ROWB + kq * 16) = pack4(xa[r]);
        }
        #pragma unroll
        for (int r = 0; r < 2; r++) {
            int slot = r * THREADS + tid;
            int e = slot >> 3, kq = slot & 7;
            *(uint4*)(Bs + e * ROWB + kq * 16) = pack4(xb[r]);
        }
        __syncthreads();

        // ---- prefetch chunk c+1 ----
        if (c + 1 < NCHUNK) {
            const int k0 = (c + 1) * BK;
            #pragma unroll
            for (int r = 0; r < 4; r++) {
                int slot = r * THREADS + tid;
                int t = slot >> 3, kq = slot & 7;
                xa[r] = *(const float4*)(X + (size_t)(token0 + t) * D_MODEL + k0 + kq * 4);
            }
            #pragma unroll
            for (int r = 0; r < 2; r++) {
                int slot = r * THREADS + tid;
                int e = slot >> 3, kq = slot & 7;
                xb[r] = *(const float4*)(W + (size_t)e * D_MODEL + k0 + kq * 4);
            }
        }

        // ---- compute: 2 k16 slices x 8 ntiles x 3 split terms ----
        #pragma unroll
        for (int s = 0; s < 2; s++) {
            const int p0 = s * 8 + qid;
            uint2 a0 = lds_pair(As, r0,     p0);
            uint2 a1 = lds_pair(As, r0 + 8, p0);
            uint2 a2 = lds_pair(As, r0,     p0 + 4);
            uint2 a3 = lds_pair(As, r0 + 8, p0 + 4);
            #pragma unroll
            for (int n = 0; n < 8; n++) {
                const int e = n * 8 + grp;
                uint2 b0 = lds_pair(Bs, e, p0);
                uint2 b1 = lds_pair(Bs, e, p0 + 4);
                mma_bf16(acc[n], a0.x, a1.x, a2.x, a3.x, b0.x, b1.x); // 1*1
                mma_bf16(acc[n], a0.x, a1.x, a2.x, a3.x, b0.y, b1.y); // 1*2
                mma_bf16(acc[n], a0.y, a1.y, a2.y, a3.y, b0.x, b1.x); // 2*1
            }
        }
    }

    // ------------------------------------------------------------------
    // epilogue: stage logits, per-token top-4 scan, gap test
    // ------------------------------------------------------------------
    __syncthreads();
    float* L = (float*)(smem + SM_AS);   // L[t][e] at t*LSTRIDE + e
    #pragma unroll
    for (int n = 0; n < 8; n++) {
        int e0 = n * 8 + 2 * qid;
        L[r0 * LSTRIDE + e0]           = acc[n][0];
        L[r0 * LSTRIDE + e0 + 1]       = acc[n][1];
        L[(r0 + 8) * LSTRIDE + e0]     = acc[n][2];
        L[(r0 + 8) * LSTRIDE + e0 + 1] = acc[n][3];
    }
    __syncthreads();

    if (tid < BM) {
        const float* Lr = L + tid * LSTRIDE;
        float tv0 = -1e30f, tv1 = -1e30f, tv2 = -1e30f, tv3 = -1e30f;
        int   ti0 = 0, ti1 = 0, ti2 = 0, ti3 = 0;
        #pragma unroll
        for (int e = 0; e < NUM_EXPERTS; e++) {
            float v = Lr[e] + bias_s[e];
            if (v > tv0) {
                tv3 = tv2; ti3 = ti2; tv2 = tv1; ti2 = ti1;
                tv1 = tv0; ti1 = ti0; tv0 = v;  ti0 = e;
            } else if (v > tv1) {
                tv3 = tv2; ti3 = ti2; tv2 = tv1; ti2 = ti1; tv1 = v; ti1 = e;
            } else if (v > tv2) {
                tv3 = tv2; ti3 = ti2; tv2 = v;  ti2 = e;
            } else if (v > tv3) {
                tv3 = v; ti3 = e;
            }
        }

        const int token = token0 + tid;
        if ((tv0 - tv1) < GAP_THRESH || (tv1 - tv2) < GAP_THRESH) {
            unsigned int idx = atomicAdd(&g_refine_ctr, 1u);
            int* rec = &g_refine_rec[idx * 5];
            rec[0] = token; rec[1] = ti0; rec[2] = ti1; rec[3] = ti2; rec[4] = ti3;
            // outputs for this token are written by router_refine
        } else {
            float r  = expf(tv1 - tv0);
            float w1 = 1.0f / (1.0f + r);
            float w2 = r / (1.0f + r);
            out[token * 2 + 0] = w1;
            out[token * 2 + 1] = w2;
            out[N_TOKENS * 2 + token * 2 + 0] = (float)ti0;
            out[N_TOKENS * 2 + token * 2 + 1] = (float)ti1;
        }
    }
}

// ---------------------------------------------------------------------------
// Kernel 2: fp64 refinement of flagged tokens (one warp per record),
// then resets the counters for the next graph replay (last block).
// ---------------------------------------------------------------------------
__global__ __launch_bounds__(256)
void router_refine(const float* __restrict__ X, const float* __restrict__ W,
                   const float* __restrict__ bias, float* __restrict__ out) {
    const unsigned int nrec = *(volatile unsigned int*)&g_refine_ctr;
    const int lane  = threadIdx.x & 31;
    const int wgid  = blockIdx.x * (blockDim.x >> 5) + (threadIdx.x >> 5);
    const int wstep = gridDim.x * (blockDim.x >> 5);

    for (unsigned int r = wgid; r < nrec; r += wstep) {
        const int* rec = &g_refine_rec[r * 5];
        const int token = rec[0];
        const float* xr = X + (size_t)token * D_MODEL;

        double lv[4];
        #pragma unroll
        for (int c = 0; c < 4; c++) {
            const int e = rec[1 + c];
            const float* wr = W + (size_t)e * D_MODEL;
            double s0 = 0.0, s1 = 0.0, s2 = 0.0, s3 = 0.0;
            #pragma unroll 4
            for (int k = lane; k < D_MODEL; k += 128) {
                s0 += (double)xr[k]      * (double)wr[k];
                s1 += (double)xr[k + 32] * (double)wr[k + 32];
                s2 += (double)xr[k + 64] * (double)wr[k + 64];
                s3 += (double)xr[k + 96] * (double)wr[k + 96];
            }
            double s = (s0 + s1) + (s2 + s3);
            #pragma unroll
            for (int off = 16; off; off >>= 1)
                s += __shfl_down_sync(0xffffffffu, s, off);
            lv[c] = s + (double)bias[e];     // valid on lane 0
        }

        if (lane == 0) {
            int ei[4] = {rec[1], rec[2], rec[3], rec[4]};
            #pragma unroll
            for (int i = 1; i < 4; i++) {        // insertion sort desc, tie->lower idx
                double v = lv[i]; int id = ei[i];
                int j = i - 1;
                while (j >= 0 && (lv[j] < v || (lv[j] == v && ei[j] > id))) {
                    lv[j + 1] = lv[j]; ei[j + 1] = ei[j]; j--;
                }
                lv[j + 1] = v; ei[j + 1] = id;
            }
            double rr = exp(lv[1] - lv[0]);
            double w1 = 1.0 / (1.0 + rr);
            double w2 = rr / (1.0 + rr);
            out[token * 2 + 0] = (float)w1;
            out[token * 2 + 1] = (float)w2;
            out[N_TOKENS * 2 + token * 2 + 0] = (float)ei[0];
            out[N_TOKENS * 2 + token * 2 + 1] = (float)ei[1];
        }
    }

    // last block to finish resets the counters for the next replay
    __syncthreads();
    if (threadIdx.x == 0) {
        __threadfence();
        unsigned int v = atomicAdd(&g_done_ctr, 1u);
        if (v == gridDim.x - 1) {
            g_refine_ctr = 0u;
            g_done_ctr = 0u;
            __threadfence();
        }
    }
}

// ---------------------------------------------------------------------------
extern "C" void kernel_launch(void* const* d_in, const int* in_sizes, int n_in,
                              void* d_out, int out_size) {
    const float* X = (const float*)d_in[0];   // [4, 4096, 2048]
    const float* W = (const float*)d_in[1];   // [64, 2048]
    const float* b = (const float*)d_in[2];   // [64]
    float* out = (float*)d_out;

    router_gemm<<<N_TOKENS / BM, THREADS, SMEM_TOTAL>>>(X, W, b, out);
    router_refine<<<128, 256>>>(X, W, b, out);
}

// round 9
// speedup vs baseline: 1.3533x; 1.1270x over previous
#include <cuda_runtime.h>
#include <cstdint>
#include <math.h>

#define D_MODEL     2048
#define NUM_EXPERTS 64
#define N_TOKENS    16384
#define BM          128                 // tokens per CTA
#define BK          32                  // K per chunk
#define NCHUNK      (D_MODEL / BK)      // 64
#define THREADS     256                 // 8 warps x 16 tokens
#define ROWB        160                 // bytes per smem row (128 data + 32 pad)
#define GAP_THRESH  3e-4f               // refine if approx top-gap below this (30x err)
#define LSTRIDE     65                  // logit staging stride (floats)

// smem: bias 256B | double-buffered {As 128x160, Bs 64x160}
#define SM_BIAS     0
#define SM_BUF      256
#define ASIZE       (BM * ROWB)                       // 20480
#define BUFSTRIDE   (ASIZE + NUM_EXPERTS * ROWB)      // 30720
#define SMEM_TOTAL  (SM_BUF + 2 * BUFSTRIDE)          // 61696 (needs attr > 48K)

// refinement records: [token, e0, e1, e2, e3]
__device__ unsigned int g_refine_ctr;
__device__ unsigned int g_done_ctr;
__device__ int g_refine_rec[N_TOKENS * 5];

// ---------------------------------------------------------------------------
static __device__ __forceinline__ uint32_t bf16x2_rn(float lo, float hi) {
    uint32_t r;
    asm("cvt.rn.bf16x2.f32 %0, %1, %2;" : "=r"(r) : "f"(hi), "f"(lo));
    return r;
}
static __device__ __forceinline__ float bf16_lo_f(uint32_t u) {
    return __uint_as_float(u << 16);
}
static __device__ __forceinline__ float bf16_hi_f(uint32_t u) {
    return __uint_as_float(u & 0xffff0000u);
}
// fp32 pair -> 2 bf16 planes {b1, b2}
static __device__ __forceinline__ uint2 split_pair(float x, float y) {
    uint32_t b1 = bf16x2_rn(x, y);
    float r1x = x - bf16_lo_f(b1);
    float r1y = y - bf16_hi_f(b1);
    uint32_t b2 = bf16x2_rn(r1x, r1y);
    return make_uint2(b1, b2);
}
static __device__ __forceinline__ uint4 pack4(const float4& v) {
    uint2 p0 = split_pair(v.x, v.y);
    uint2 p1 = split_pair(v.z, v.w);
    return make_uint4(p0.x, p0.y, p1.x, p1.y);
}
static __device__ __forceinline__ uint2 lds_pair(const char* base, int row, int p) {
    return *(const uint2*)(base + row * ROWB + p * 8);
}

static __device__ __forceinline__ void mma_bf16(float* d,
                                                uint32_t a0, uint32_t a1,
                                                uint32_t a2, uint32_t a3,
                                                uint32_t b0, uint32_t b1) {
    asm volatile(
        "mma.sync.aligned.m16n8k16.row.col.f32.bf16.bf16.f32 "
        "{%0,%1,%2,%3}, {%4,%5,%6,%7}, {%8,%9}, {%0,%1,%2,%3};"
        : "+f"(d[0]), "+f"(d[1]), "+f"(d[2]), "+f"(d[3])
        : "r"(a0), "r"(a1), "r"(a2), "r"(a3), "r"(b0), "r"(b1));
}

// ---------------------------------------------------------------------------
// Kernel 1: bf16x3 split GEMM, double-buffered smem, 1 barrier per chunk.
// ---------------------------------------------------------------------------
__global__ __launch_bounds__(THREADS)
void router_gemm(const float* __restrict__ X, const float* __restrict__ W,
                 const float* __restrict__ bias, float* __restrict__ out) {
    extern __shared__ __align__(16) char smem[];
    float* bias_s = (float*)(smem + SM_BIAS);
    char*  bufs   = smem + SM_BUF;

    const int tid  = threadIdx.x;
    const int wid  = tid >> 5;
    const int lane = tid & 31;
    const int grp  = lane >> 2;     // 0..7
    const int qid  = lane & 3;      // 0..3
    const int token0 = blockIdx.x * BM;
    const int r0 = wid * 16 + grp;  // warp tile: 16 tokens x 64 experts

    // per-thread load slots
    const int tA[4] = { (0*THREADS+tid)>>3, (1*THREADS+tid)>>3,
                        (2*THREADS+tid)>>3, (3*THREADS+tid)>>3 };
    const int eB[2] = { (0*THREADS+tid)>>3, (1*THREADS+tid)>>3 };
    const int kq = tid & 7;

    if (tid < NUM_EXPERTS) bias_s[tid] = bias[tid];

    float acc[8][4];
    #pragma unroll
    for (int n = 0; n < 8; n++)
        #pragma unroll
        for (int r = 0; r < 4; r++) acc[n][r] = 0.0f;

    float4 xa[4], xb[2];
    // prologue: chunk 0 -> buf0 ; chunk 1 -> regs
    #pragma unroll
    for (int r = 0; r < 4; r++)
        xa[r] = *(const float4*)(X + (size_t)(token0 + tA[r]) * D_MODEL + kq * 4);
    #pragma unroll
    for (int r = 0; r < 2; r++)
        xb[r] = *(const float4*)(W + (size_t)eB[r] * D_MODEL + kq * 4);
    #pragma unroll
    for (int r = 0; r < 4; r++)
        *(uint4*)(bufs + tA[r] * ROWB + kq * 16) = pack4(xa[r]);
    #pragma unroll
    for (int r = 0; r < 2; r++)
        *(uint4*)(bufs + ASIZE + eB[r] * ROWB + kq * 16) = pack4(xb[r]);
    #pragma unroll
    for (int r = 0; r < 4; r++)
        xa[r] = *(const float4*)(X + (size_t)(token0 + tA[r]) * D_MODEL + BK + kq * 4);
    #pragma unroll
    for (int r = 0; r < 2; r++)
        xb[r] = *(const float4*)(W + (size_t)eB[r] * D_MODEL + BK + kq * 4);
    __syncthreads();

    #pragma unroll 1
    for (int c = 0; c < NCHUNK; c++) {
        char* cur = bufs + (c & 1) * BUFSTRIDE;
        char* nxt = bufs + ((c + 1) & 1) * BUFSTRIDE;

        // store chunk c+1 (regs) into idle buffer
        if (c + 1 < NCHUNK) {
            #pragma unroll
            for (int r = 0; r < 4; r++)
                *(uint4*)(nxt + tA[r] * ROWB + kq * 16) = pack4(xa[r]);
            #pragma unroll
            for (int r = 0; r < 2; r++)
                *(uint4*)(nxt + ASIZE + eB[r] * ROWB + kq * 16) = pack4(xb[r]);
        }
        // prefetch chunk c+2
        if (c + 2 < NCHUNK) {
            const int k0 = (c + 2) * BK;
            #pragma unroll
            for (int r = 0; r < 4; r++)
                xa[r] = *(const float4*)(X + (size_t)(token0 + tA[r]) * D_MODEL + k0 + kq * 4);
            #pragma unroll
            for (int r = 0; r < 2; r++)
                xb[r] = *(const float4*)(W + (size_t)eB[r] * D_MODEL + k0 + kq * 4);
        }

        // compute chunk c: 2 k16 slices x 8 ntiles x 3 split terms
        const char* As = cur;
        const char* Bs = cur + ASIZE;
        #pragma unroll
        for (int s = 0; s < 2; s++) {
            const int p0 = s * 8 + qid;
            uint2 a0 = lds_pair(As, r0,     p0);
            uint2 a1 = lds_pair(As, r0 + 8, p0);
            uint2 a2 = lds_pair(As, r0,     p0 + 4);
            uint2 a3 = lds_pair(As, r0 + 8, p0 + 4);
            #pragma unroll
            for (int n = 0; n < 8; n++) {
                const int e = n * 8 + grp;
                uint2 b0 = lds_pair(Bs, e, p0);
                uint2 b1 = lds_pair(Bs, e, p0 + 4);
                mma_bf16(acc[n], a0.x, a1.x, a2.x, a3.x, b0.x, b1.x); // 1*1
                mma_bf16(acc[n], a0.x, a1.x, a2.x, a3.x, b0.y, b1.y); // 1*2
                mma_bf16(acc[n], a0.y, a1.y, a2.y, a3.y, b0.x, b1.x); // 2*1
            }
        }
        __syncthreads();
    }

    // ------------------------------------------------------------------
    // epilogue: stage logits, per-token top-4 scan, gap test
    // ------------------------------------------------------------------
    float* L = (float*)(smem + SM_BUF);   // L[t][e] at t*LSTRIDE + e
    #pragma unroll
    for (int n = 0; n < 8; n++) {
        int e0 = n * 8 + 2 * qid;
        L[r0 * LSTRIDE + e0]           = acc[n][0];
        L[r0 * LSTRIDE + e0 + 1]       = acc[n][1];
        L[(r0 + 8) * LSTRIDE + e0]     = acc[n][2];
        L[(r0 + 8) * LSTRIDE + e0 + 1] = acc[n][3];
    }
    __syncthreads();

    if (tid < BM) {
        const float* Lr = L + tid * LSTRIDE;
        float tv0 = -1e30f, tv1 = -1e30f, tv2 = -1e30f, tv3 = -1e30f;
        int   ti0 = 0, ti1 = 0, ti2 = 0, ti3 = 0;
        #pragma unroll
        for (int e = 0; e < NUM_EXPERTS; e++) {
            float v = Lr[e] + bias_s[e];
            if (v > tv0) {
                tv3 = tv2; ti3 = ti2; tv2 = tv1; ti2 = ti1;
                tv1 = tv0; ti1 = ti0; tv0 = v;  ti0 = e;
            } else if (v > tv1) {
                tv3 = tv2; ti3 = ti2; tv2 = tv1; ti2 = ti1; tv1 = v; ti1 = e;
            } else if (v > tv2) {
                tv3 = tv2; ti3 = ti2; tv2 = v;  ti2 = e;
            } else if (v > tv3) {
                tv3 = v; ti3 = e;
            }
        }

        const int token = token0 + tid;
        if ((tv0 - tv1) < GAP_THRESH || (tv1 - tv2) < GAP_THRESH) {
            unsigned int idx = atomicAdd(&g_refine_ctr, 1u);
            int* rec = &g_refine_rec[idx * 5];
            rec[0] = token; rec[1] = ti0; rec[2] = ti1; rec[3] = ti2; rec[4] = ti3;
            // outputs written by router_refine
        } else {
            float r  = expf(tv1 - tv0);
            float w1 = 1.0f / (1.0f + r);
            float w2 = r / (1.0f + r);
            out[token * 2 + 0] = w1;
            out[token * 2 + 1] = w2;
            out[N_TOKENS * 2 + token * 2 + 0] = (float)ti0;
            out[N_TOKENS * 2 + token * 2 + 1] = (float)ti1;
        }
    }
}

// ---------------------------------------------------------------------------
// Kernel 2: fp64 refinement (one warp per record, 4 experts interleaved),
// then last block resets counters for the next graph replay.
// ---------------------------------------------------------------------------
__global__ __launch_bounds__(256)
void router_refine(const float* __restrict__ X, const float* __restrict__ W,
                   const float* __restrict__ bias, float* __restrict__ out) {
    const unsigned int nrec = *(volatile unsigned int*)&g_refine_ctr;
    const int lane  = threadIdx.x & 31;
    const int wgid  = blockIdx.x * (blockDim.x >> 5) + (threadIdx.x >> 5);
    const int wstep = gridDim.x * (blockDim.x >> 5);

    for (unsigned int r = wgid; r < nrec; r += wstep) {
        const int* rec = &g_refine_rec[r * 5];
        const int token = rec[0];
        const float* xr = X + (size_t)token * D_MODEL;
        const float* w0 = W + (size_t)rec[1] * D_MODEL;
        const float* w1 = W + (size_t)rec[2] * D_MODEL;
        const float* w2 = W + (size_t)rec[3] * D_MODEL;
        const float* w3 = W + (size_t)rec[4] * D_MODEL;

        double a0[4] = {0, 0, 0, 0}, a1[4] = {0, 0, 0, 0};
        #pragma unroll 4
        for (int k = lane; k < D_MODEL; k += 64) {
            double x0 = (double)xr[k], x1 = (double)xr[k + 32];
            a0[0] += x0 * (double)w0[k];  a1[0] += x1 * (double)w0[k + 32];
            a0[1] += x0 * (double)w1[k];  a1[1] += x1 * (double)w1[k + 32];
            a0[2] += x0 * (double)w2[k];  a1[2] += x1 * (double)w2[k + 32];
            a0[3] += x0 * (double)w3[k];  a1[3] += x1 * (double)w3[k + 32];
        }

        double lv[4];
        #pragma unroll
        for (int c = 0; c < 4; c++) {
            double s = a0[c] + a1[c];
            #pragma unroll
            for (int off = 16; off; off >>= 1)
                s += __shfl_down_sync(0xffffffffu, s, off);
            lv[c] = s + (double)bias[rec[1 + c]];   // valid on lane 0
        }

        if (lane == 0) {
            int ei[4] = {rec[1], rec[2], rec[3], rec[4]};
            #pragma unroll
            for (int i = 1; i < 4; i++) {        // insertion sort desc, tie->lower idx
                double v = lv[i]; int id = ei[i];
                int j = i - 1;
                while (j >= 0 && (lv[j] < v || (lv[j] == v && ei[j] > id))) {
                    lv[j + 1] = lv[j]; ei[j + 1] = ei[j]; j--;
                }
                lv[j + 1] = v; ei[j + 1] = id;
            }
            double rr = exp(lv[1] - lv[0]);
            out[token * 2 + 0] = (float)(1.0 / (1.0 + rr));
            out[token * 2 + 1] = (float)(rr / (1.0 + rr));
            out[N_TOKENS * 2 + token * 2 + 0] = (float)ei[0];
            out[N_TOKENS * 2 + token * 2 + 1] = (float)ei[1];
        }
    }

    // last block to finish resets the counters for the next replay
    __syncthreads();
    if (threadIdx.x == 0) {
        __threadfence();
        unsigned int v = atomicAdd(&g_done_ctr, 1u);
        if (v == gridDim.x - 1) {
            g_refine_ctr = 0u;
            g_done_ctr = 0u;
            __threadfence();
        }
    }
}

// ---------------------------------------------------------------------------
extern "C" void kernel_launch(void* const* d_in, const int* in_sizes, int n_in,
                              void* d_out, int out_size) {
    const float* X = (const float*)d_in[0];   // [4, 4096, 2048]
    const float* W = (const float*)d_in[1];   // [64, 2048]
    const float* b = (const float*)d_in[2];   // [64]
    float* out = (float*)d_out;

    static int configured = 0;
    if (!configured) {
        cudaFuncSetAttribute(router_gemm,
                             cudaFuncAttributeMaxDynamicSharedMemorySize, SMEM_TOTAL);
        configured = 1;
    }
    router_gemm<<<N_TOKENS / BM, THREADS, SMEM_TOTAL>>>(X, W, b, out);
    router_refine<<<128, 256>>>(X, W, b, out);
}

// round 10
// speedup vs baseline: 1.7597x; 1.3004x over previous
#include <cuda_runtime.h>
#include <cstdint>
#include <math.h>

#define D_MODEL     2048
#define NUM_EXPERTS 64
#define N_TOKENS    16384
#define BM          64                  // tokens per CTA
#define BK          32                  // K per chunk
#define NCHUNK      (D_MODEL / BK)      // 64
#define THREADS     128                 // 4 warps x 16 tokens
#define ROWB        160                 // bytes per smem row (128 data + 32 pad)
#define GAP_THRESH  3e-4f               // refine if approx top-gap below this
#define LSTRIDE     65                  // logit staging stride (floats)

// smem: bias 256B | double-buffered {As 64x160, Bs 64x160}
// epilogue reuse: L[64][65] floats at SM_BUF (16640B), flag list at +20480
#define SM_BIAS     0
#define SM_BUF      256
#define ASIZE       (BM * ROWB)                       // 10240
#define BUFSTRIDE   (ASIZE + NUM_EXPERTS * ROWB)      // 20480
#define SM_FLAGS    (SM_BUF + BUFSTRIDE)              // 20736 (inside buffer 1)
#define SMEM_TOTAL  (SM_BUF + 2 * BUFSTRIDE)          // 41216 (< 48K)

// ---------------------------------------------------------------------------
static __device__ __forceinline__ uint32_t bf16x2_rn(float lo, float hi) {
    uint32_t r;
    asm("cvt.rn.bf16x2.f32 %0, %1, %2;" : "=r"(r) : "f"(hi), "f"(lo));
    return r;
}
static __device__ __forceinline__ float bf16_lo_f(uint32_t u) {
    return __uint_as_float(u << 16);
}
static __device__ __forceinline__ float bf16_hi_f(uint32_t u) {
    return __uint_as_float(u & 0xffff0000u);
}
// fp32 pair -> 2 bf16 planes {b1, b2}
static __device__ __forceinline__ uint2 split_pair(float x, float y) {
    uint32_t b1 = bf16x2_rn(x, y);
    float r1x = x - bf16_lo_f(b1);
    float r1y = y - bf16_hi_f(b1);
    uint32_t b2 = bf16x2_rn(r1x, r1y);
    return make_uint2(b1, b2);
}
static __device__ __forceinline__ uint4 pack4(const float4& v) {
    uint2 p0 = split_pair(v.x, v.y);
    uint2 p1 = split_pair(v.z, v.w);
    return make_uint4(p0.x, p0.y, p1.x, p1.y);
}
static __device__ __forceinline__ uint2 lds_pair(const char* base, int row, int p) {
    return *(const uint2*)(base + row * ROWB + p * 8);
}

static __device__ __forceinline__ void mma_bf16(float* d,
                                                uint32_t a0, uint32_t a1,
                                                uint32_t a2, uint32_t a3,
                                                uint32_t b0, uint32_t b1) {
    asm volatile(
        "mma.sync.aligned.m16n8k16.row.col.f32.bf16.bf16.f32 "
        "{%0,%1,%2,%3}, {%4,%5,%6,%7}, {%8,%9}, {%0,%1,%2,%3};"
        : "+f"(d[0]), "+f"(d[1]), "+f"(d[2]), "+f"(d[3])
        : "r"(a0), "r"(a1), "r"(a2), "r"(a3), "r"(b0), "r"(b1));
}

// ---------------------------------------------------------------------------
// Fused: bf16x3 split GEMM (double-buffered) + top-4 gap test + in-CTA fp64
// refinement of near-tie tokens. One kernel, no global scratch.
// ---------------------------------------------------------------------------
__global__ __launch_bounds__(THREADS)
void router_fused(const float* __restrict__ X, const float* __restrict__ W,
                  const float* __restrict__ bias, float* __restrict__ out) {
    extern __shared__ __align__(16) char smem[];
    float* bias_s = (float*)(smem + SM_BIAS);
    char*  bufs   = smem + SM_BUF;

    const int tid  = threadIdx.x;
    const int wid  = tid >> 5;
    const int lane = tid & 31;
    const int grp  = lane >> 2;     // 0..7
    const int qid  = lane & 3;      // 0..3
    const int token0 = blockIdx.x * BM;
    const int r0 = wid * 16 + grp;  // warp tile: 16 tokens x 64 experts

    // per-thread load slots (A: 4 float4, B: 4 float4)
    const int tA[4] = { (0*THREADS+tid)>>3, (1*THREADS+tid)>>3,
                        (2*THREADS+tid)>>3, (3*THREADS+tid)>>3 };
    const int kq = tid & 7;

    if (tid < NUM_EXPERTS) bias_s[tid] = bias[tid];

    float acc[8][4];
    #pragma unroll
    for (int n = 0; n < 8; n++)
        #pragma unroll
        for (int r = 0; r < 4; r++) acc[n][r] = 0.0f;

    float4 xa[4], xb[4];
    // prologue: chunk 0 -> buf0 ; chunk 1 -> regs
    #pragma unroll
    for (int r = 0; r < 4; r++) {
        xa[r] = *(const float4*)(X + (size_t)(token0 + tA[r]) * D_MODEL + kq * 4);
        xb[r] = *(const float4*)(W + (size_t)tA[r] * D_MODEL + kq * 4);
    }
    #pragma unroll
    for (int r = 0; r < 4; r++) {
        *(uint4*)(bufs + tA[r] * ROWB + kq * 16)         = pack4(xa[r]);
        *(uint4*)(bufs + ASIZE + tA[r] * ROWB + kq * 16) = pack4(xb[r]);
    }
    #pragma unroll
    for (int r = 0; r < 4; r++) {
        xa[r] = *(const float4*)(X + (size_t)(token0 + tA[r]) * D_MODEL + BK + kq * 4);
        xb[r] = *(const float4*)(W + (size_t)tA[r] * D_MODEL + BK + kq * 4);
    }
    __syncthreads();

    #pragma unroll 1
    for (int c = 0; c < NCHUNK; c++) {
        char* cur = bufs + (c & 1) * BUFSTRIDE;
        char* nxt = bufs + ((c + 1) & 1) * BUFSTRIDE;

        // store chunk c+1 (regs) into idle buffer
        if (c + 1 < NCHUNK) {
            #pragma unroll
            for (int r = 0; r < 4; r++) {
                *(uint4*)(nxt + tA[r] * ROWB + kq * 16)         = pack4(xa[r]);
                *(uint4*)(nxt + ASIZE + tA[r] * ROWB + kq * 16) = pack4(xb[r]);
            }
        }
        // prefetch chunk c+2
        if (c + 2 < NCHUNK) {
            const int k0 = (c + 2) * BK;
            #pragma unroll
            for (int r = 0; r < 4; r++) {
                xa[r] = *(const float4*)(X + (size_t)(token0 + tA[r]) * D_MODEL + k0 + kq * 4);
                xb[r] = *(const float4*)(W + (size_t)tA[r] * D_MODEL + k0 + kq * 4);
            }
        }

        // compute chunk c: 2 k16 slices x 8 ntiles x 3 split terms
        const char* As = cur;
        const char* Bs = cur + ASIZE;
        #pragma unroll
        for (int s = 0; s < 2; s++) {
            const int p0 = s * 8 + qid;
            uint2 a0 = lds_pair(As, r0,     p0);
            uint2 a1 = lds_pair(As, r0 + 8, p0);
            uint2 a2 = lds_pair(As, r0,     p0 + 4);
            uint2 a3 = lds_pair(As, r0 + 8, p0 + 4);
            #pragma unroll
            for (int n = 0; n < 8; n++) {
                const int e = n * 8 + grp;
                uint2 b0 = lds_pair(Bs, e, p0);
                uint2 b1 = lds_pair(Bs, e, p0 + 4);
                mma_bf16(acc[n], a0.x, a1.x, a2.x, a3.x, b0.x, b1.x); // 1*1
                mma_bf16(acc[n], a0.x, a1.x, a2.x, a3.x, b0.y, b1.y); // 1*2
                mma_bf16(acc[n], a0.y, a1.y, a2.y, a3.y, b0.x, b1.x); // 2*1
            }
        }
        __syncthreads();
    }

    // ------------------------------------------------------------------
    // epilogue: stage logits, per-token top-4 scan, gap test
    // ------------------------------------------------------------------
    float* L      = (float*)(smem + SM_BUF);     // L[t][e] at t*LSTRIDE+e (16640B)
    int*   flags  = (int*)(smem + SM_FLAGS);     // [0]=count, then 5 ints/record

    #pragma unroll
    for (int n = 0; n < 8; n++) {
        int e0 = n * 8 + 2 * qid;
        L[r0 * LSTRIDE + e0]           = acc[n][0];
        L[r0 * LSTRIDE + e0 + 1]       = acc[n][1];
        L[(r0 + 8) * LSTRIDE + e0]     = acc[n][2];
        L[(r0 + 8) * LSTRIDE + e0 + 1] = acc[n][3];
    }
    if (tid == 0) flags[0] = 0;
    __syncthreads();

    if (tid < BM) {
        const float* Lr = L + tid * LSTRIDE;
        float tv0 = -1e30f, tv1 = -1e30f, tv2 = -1e30f, tv3 = -1e30f;
        int   ti0 = 0, ti1 = 0, ti2 = 0, ti3 = 0;
        #pragma unroll
        for (int e = 0; e < NUM_EXPERTS; e++) {
            float v = Lr[e] + bias_s[e];
            if (v > tv0) {
                tv3 = tv2; ti3 = ti2; tv2 = tv1; ti2 = ti1;
                tv1 = tv0; ti1 = ti0; tv0 = v;  ti0 = e;
            } else if (v > tv1) {
                tv3 = tv2; ti3 = ti2; tv2 = tv1; ti2 = ti1; tv1 = v; ti1 = e;
            } else if (v > tv2) {
                tv3 = tv2; ti3 = ti2; tv2 = v;  ti2 = e;
            } else if (v > tv3) {
                tv3 = v; ti3 = e;
            }
        }

        const int token = token0 + tid;
        if ((tv0 - tv1) < GAP_THRESH || (tv1 - tv2) < GAP_THRESH) {
            int idx = atomicAdd(&flags[0], 1);
            int* rec = &flags[1 + idx * 5];
            rec[0] = token; rec[1] = ti0; rec[2] = ti1; rec[3] = ti2; rec[4] = ti3;
        } else {
            float r  = expf(tv1 - tv0);
            out[token * 2 + 0] = 1.0f / (1.0f + r);
            out[token * 2 + 1] = r / (1.0f + r);
            out[N_TOKENS * 2 + token * 2 + 0] = (float)ti0;
            out[N_TOKENS * 2 + token * 2 + 1] = (float)ti1;
        }
    }
    __syncthreads();

    // ------------------------------------------------------------------
    // in-CTA fp64 refinement of flagged tokens (one warp per record)
    // ------------------------------------------------------------------
    const int nrec = flags[0];
    for (int r = wid; r < nrec; r += 4) {
        const int* rec = &flags[1 + r * 5];
        const int token = rec[0];
        const float* xr = X + (size_t)token * D_MODEL;
        const float* w0 = W + (size_t)rec[1] * D_MODEL;
        const float* w1 = W + (size_t)rec[2] * D_MODEL;
        const float* w2 = W + (size_t)rec[3] * D_MODEL;
        const float* w3 = W + (size_t)rec[4] * D_MODEL;

        double a0[4] = {0, 0, 0, 0}, a1[4] = {0, 0, 0, 0};
        #pragma unroll 4
        for (int k = lane; k < D_MODEL; k += 64) {
            double x0 = (double)xr[k], x1 = (double)xr[k + 32];
            a0[0] += x0 * (double)w0[k];  a1[0] += x1 * (double)w0[k + 32];
            a0[1] += x0 * (double)w1[k];  a1[1] += x1 * (double)w1[k + 32];
            a0[2] += x0 * (double)w2[k];  a1[2] += x1 * (double)w2[k + 32];
            a0[3] += x0 * (double)w3[k];  a1[3] += x1 * (double)w3[k + 32];
        }

        double lv[4];
        #pragma unroll
        for (int c = 0; c < 4; c++) {
            double s = a0[c] + a1[c];
            #pragma unroll
            for (int off = 16; off; off >>= 1)
                s += __shfl_down_sync(0xffffffffu, s, off);
            lv[c] = s + (double)bias_s[rec[1 + c]];   // valid on lane 0
        }

        if (lane == 0) {
            int ei[4] = {rec[1], rec[2], rec[3], rec[4]};
            #pragma unroll
            for (int i = 1; i < 4; i++) {        // insertion sort desc, tie->lower idx
                double v = lv[i]; int id = ei[i];
                int j = i - 1;
                while (j >= 0 && (lv[j] < v || (lv[j] == v && ei[j] > id))) {
                    lv[j + 1] = lv[j]; ei[j + 1] = ei[j]; j--;
                }
                lv[j + 1] = v; ei[j + 1] = id;
            }
            double rr = exp(lv[1] - lv[0]);
            out[token * 2 + 0] = (float)(1.0 / (1.0 + rr));
            out[token * 2 + 1] = (float)(rr / (1.0 + rr));
            out[N_TOKENS * 2 + token * 2 + 0] = (float)ei[0];
            out[N_TOKENS * 2 + token * 2 + 1] = (float)ei[1];
        }
    }
}

// ---------------------------------------------------------------------------
extern "C" void kernel_launch(void* const* d_in, const int* in_sizes, int n_in,
                              void* d_out, int out_size) {
    const float* X = (const float*)d_in[0];   // [4, 4096, 2048]
    const float* W = (const float*)d_in[1];   // [64, 2048]
    const float* b = (const float*)d_in[2];   // [64]
    float* out = (float*)d_out;

    router_fused<<<N_TOKENS / BM, THREADS, SMEM_TOTAL>>>(X, W, b, out);
}